// round 1
// baseline (speedup 1.0000x reference)
#include <cuda_runtime.h>
#include <cstdint>

#define NNODES 20000
#define NEDGES 320000
#define DM 128
#define PREDL 24

// ---------------- scratch (device globals; no allocation allowed) -------------
__device__ float g_h[NNODES * DM];           // node state  (10.2 MB)
__device__ float g_e[(size_t)NEDGES * DM];   // edge state  (164 MB)
__device__ float g_agg[NNODES * DM];         // scatter-sum (10.2 MB)
__device__ float g_cnt[NNODES];              // in-degree

// ---------------- packed f32x2 helpers ---------------------------------------
__device__ __forceinline__ unsigned long long pack2(float x, float y) {
    unsigned long long r;
    asm("mov.b64 %0, {%1, %2};" : "=l"(r) : "f"(x), "f"(y));
    return r;
}
__device__ __forceinline__ void fma2(unsigned long long& a, unsigned long long x,
                                     unsigned long long y) {
    asm("fma.rn.f32x2 %0, %1, %2, %0;" : "+l"(a) : "l"(x), "l"(y));
}

union Acc { unsigned long long u[16]; float f[32]; };

// ---------------- shared tiled GEMM core --------------------------------------
// C[64,128] = A^T-stored-input[K][65-strided, 64 rows] @ W[K,128] + bias
// 256 threads: tx=tid&15 -> cols c0=tx*8 ; ty=tid>>4 -> rows r0=ty*4
// Columns packed in pairs for fma.rn.f32x2 (2x fp32 throughput on sm_103a).
__device__ __forceinline__ void gemm_tile(
    const float* __restrict__ W, const float* __restrict__ bias, int K,
    const float* __restrict__ sIn, float* __restrict__ sB, Acc& A,
    int tid, int c0, int r0)
{
#pragma unroll
    for (int p = 0; p < 4; p++) {
        unsigned long long bp = pack2(bias[c0 + 2 * p], bias[c0 + 2 * p + 1]);
        A.u[p] = bp; A.u[4 + p] = bp; A.u[8 + p] = bp; A.u[12 + p] = bp;
    }
    for (int kc = 0; kc < K; kc += 32) {
        // stage 32x128 W chunk (16 KB) into smem
        const float4* Wv = (const float4*)(W + kc * 128);
        float4* sBv = (float4*)sB;
#pragma unroll
        for (int i = 0; i < 4; i++) sBv[tid + i * 256] = Wv[tid + i * 256];
        __syncthreads();
#pragma unroll 8
        for (int kk = 0; kk < 32; kk++) {
            const float* ar = sIn + (kc + kk) * 65 + r0;
            unsigned long long a0 = pack2(ar[0], ar[0]);
            unsigned long long a1 = pack2(ar[1], ar[1]);
            unsigned long long a2 = pack2(ar[2], ar[2]);
            unsigned long long a3 = pack2(ar[3], ar[3]);
            const unsigned long long* br =
                (const unsigned long long*)(sB + kk * 128 + c0);
            unsigned long long b0 = br[0], b1 = br[1], b2 = br[2], b3 = br[3];
            fma2(A.u[0],  a0, b0); fma2(A.u[1],  a0, b1);
            fma2(A.u[2],  a0, b2); fma2(A.u[3],  a0, b3);
            fma2(A.u[4],  a1, b0); fma2(A.u[5],  a1, b1);
            fma2(A.u[6],  a1, b2); fma2(A.u[7],  a1, b3);
            fma2(A.u[8],  a2, b0); fma2(A.u[9],  a2, b1);
            fma2(A.u[10], a2, b2); fma2(A.u[11], a2, b3);
            fma2(A.u[12], a3, b0); fma2(A.u[13], a3, b1);
            fma2(A.u[14], a3, b2); fma2(A.u[15], a3, b3);
        }
        __syncthreads();
    }
}

__device__ __forceinline__ float gelu_tanh(float x) {
    // JAX default gelu: approximate=True (tanh form)
    float x3 = x * x * x;
    float t = tanhf(0.7978845608028654f * (x + 0.044715f * x3));
    return 0.5f * x * (1.0f + t);
}

// gelu + LayerNorm(gamma,beta) over the 128-wide row, 16-lane shuffle reduce
__device__ __forceinline__ void gelu_ln(Acc& A, const float* __restrict__ gg,
                                        const float* __restrict__ bb, int c0)
{
    float gv[8], bv[8];
#pragma unroll
    for (int j = 0; j < 8; j++) { gv[j] = gg[c0 + j]; bv[j] = bb[c0 + j]; }
#pragma unroll
    for (int i = 0; i < 32; i++) A.f[i] = gelu_tanh(A.f[i]);
#pragma unroll
    for (int r = 0; r < 4; r++) {
        float s = 0.f, q = 0.f;
#pragma unroll
        for (int j = 0; j < 8; j++) { float v = A.f[r * 8 + j]; s += v; q += v * v; }
#pragma unroll
        for (int o = 1; o < 16; o <<= 1) {
            s += __shfl_xor_sync(0xffffffffu, s, o);
            q += __shfl_xor_sync(0xffffffffu, q, o);
        }
        float m  = s * (1.0f / 128.0f);
        float vr = q * (1.0f / 128.0f) - m * m;
        float rs = rsqrtf(vr + 1e-5f);
#pragma unroll
        for (int j = 0; j < 8; j++)
            A.f[r * 8 + j] = (A.f[r * 8 + j] - m) * rs * gv[j] + bv[j];
    }
}

__device__ __forceinline__ void store_T(float* __restrict__ s, const float* acc,
                                        int c0, int r0)
{
#pragma unroll
    for (int j = 0; j < 8; j++)
#pragma unroll
        for (int r = 0; r < 4; r++)
            s[(c0 + j) * 65 + r0 + r] = acc[r * 8 + j];
}

// ---------------- kernels -----------------------------------------------------

// h = nodes.reshape(N,288) @ W + b
__global__ __launch_bounds__(256, 1) void emb_node_kernel(
    const float* __restrict__ nodes, const float* __restrict__ W,
    const float* __restrict__ bias, float* __restrict__ h)
{
    extern __shared__ float sm[];
    float* sAT = sm;              // 288*65
    float* sB  = sAT + 288 * 65; // 4096
    int tid = threadIdx.x;
    int base = blockIdx.x * 64;
    for (int i = tid; i < 64 * 72; i += 256) {
        int row = i / 72, c4 = i % 72;
        int n = min(base + row, NNODES - 1);
        float4 v = *(const float4*)(nodes + n * 288 + c4 * 4);
        float* d = sAT + (c4 * 4) * 65 + row;
        d[0] = v.x; d[65] = v.y; d[130] = v.z; d[195] = v.w;
    }
    __syncthreads();
    int tx = tid & 15, ty = tid >> 4, c0 = tx * 8, r0 = ty * 4;
    Acc A;
    gemm_tile(W, bias, 288, sAT, sB, A, tid, c0, r0);
#pragma unroll
    for (int r = 0; r < 4; r++) {
        int n = base + r0 + r;
        if (n < NNODES) {
            float* hp = h + n * DM + c0;
            *(float4*)hp       = *(float4*)&A.f[r * 8];
            *(float4*)(hp + 4) = *(float4*)&A.f[r * 8 + 4];
        }
    }
}

// e = edges(E,2) @ W(2,128) + b  (elementwise, K=2)
__global__ void emb_edge_kernel(const float* __restrict__ edges,
                                const float* __restrict__ W,
                                const float* __restrict__ bias,
                                float* __restrict__ e)
{
    int idx = blockIdx.x * 256 + threadIdx.x;   // E*32 float4 units
    if (idx >= NEDGES * 32) return;
    int ei = idx >> 5, c4 = idx & 31;
    float x0 = edges[2 * ei], x1 = edges[2 * ei + 1];
    float4 w0 = *(const float4*)(W + c4 * 4);
    float4 w1 = *(const float4*)(W + DM + c4 * 4);
    float4 b  = *(const float4*)(bias + c4 * 4);
    float4 o;
    o.x = fmaf(x0, w0.x, fmaf(x1, w1.x, b.x));
    o.y = fmaf(x0, w0.y, fmaf(x1, w1.y, b.y));
    o.z = fmaf(x0, w0.z, fmaf(x1, w1.z, b.z));
    o.w = fmaf(x0, w0.w, fmaf(x1, w1.w, b.w));
    *(float4*)(e + (size_t)ei * DM + c4 * 4) = o;
}

__global__ void count_kernel(const int* __restrict__ receivers,
                             float* __restrict__ cnt)
{
    int i = blockIdx.x * 256 + threadIdx.x;
    if (i < NEDGES) atomicAdd(&cnt[receivers[i]], 1.0f);
}

// fused edge update: e += MLP(concat(e,h[s],h[r]) @ Wp + bp); agg += e_new
__global__ __launch_bounds__(256, 1) void edge_kernel(
    const float* __restrict__ h, float* __restrict__ e,
    const int* __restrict__ senders, const int* __restrict__ receivers,
    const float* __restrict__ Wp, const float* __restrict__ bp,
    const float* __restrict__ W0, const float* __restrict__ b0,
    const float* __restrict__ g0, const float* __restrict__ be0,
    const float* __restrict__ W1, const float* __restrict__ b1,
    const float* __restrict__ g1, const float* __restrict__ be1,
    float* __restrict__ agg)
{
    extern __shared__ float sm[];
    float* sAT = sm;               // 384*65 (transposed A: cols 0..127=e, ..=h[s], ..=h[r])
    float* sX  = sAT + 384 * 65;  // 128*65 intermediate
    float* sB  = sX + 128 * 65;   // 4096 W chunk
    int* sSnd  = (int*)(sB + 4096);
    int* sRcv  = sSnd + 64;
    int tid = threadIdx.x;
    int base = blockIdx.x * 64;
    if (tid < 64)       sSnd[tid]      = senders[base + tid];
    else if (tid < 128) sRcv[tid - 64] = receivers[base + tid - 64];
    __syncthreads();
    for (int i = tid; i < 64 * 96; i += 256) {
        int row = i / 96, c4 = i % 96;
        const float* src;
        if (c4 < 32)      src = e + (size_t)(base + row) * DM + c4 * 4;
        else if (c4 < 64) src = h + (size_t)sSnd[row] * DM + (c4 - 32) * 4;
        else              src = h + (size_t)sRcv[row] * DM + (c4 - 64) * 4;
        float4 v = *(const float4*)src;
        float* d = sAT + (c4 * 4) * 65 + row;
        d[0] = v.x; d[65] = v.y; d[130] = v.z; d[195] = v.w;
    }
    __syncthreads();
    int tx = tid & 15, ty = tid >> 4, c0 = tx * 8, r0 = ty * 4;
    Acc A;
    gemm_tile(Wp, bp, 384, sAT, sB, A, tid, c0, r0);   // projection (no act)
    store_T(sX, A.f, c0, r0);
    gemm_tile(W0, b0, 128, sX, sB, A, tid, c0, r0);    // mlp layer 0
    gelu_ln(A, g0, be0, c0);
    store_T(sX, A.f, c0, r0);
    gemm_tile(W1, b1, 128, sX, sB, A, tid, c0, r0);    // mlp layer 1
    gelu_ln(A, g1, be1, c0);
#pragma unroll
    for (int r = 0; r < 4; r++) {
        int row = r0 + r;
#pragma unroll
        for (int j = 0; j < 8; j++)
            A.f[r * 8 + j] += sAT[(c0 + j) * 65 + row];  // residual (e cols intact)
        float* ep = e + (size_t)(base + row) * DM + c0;
        *(float4*)ep       = *(float4*)&A.f[r * 8];
        *(float4*)(ep + 4) = *(float4*)&A.f[r * 8 + 4];
        float* ag = agg + (size_t)sRcv[row] * DM + c0;
#pragma unroll
        for (int j = 0; j < 8; j++) atomicAdd(ag + j, A.f[r * 8 + j]);
    }
}

// fused node update: h += MLP(concat(h, agg/cnt) @ Wp + bp)
__global__ __launch_bounds__(256, 1) void node_kernel(
    float* __restrict__ h, const float* __restrict__ agg,
    const float* __restrict__ cnt,
    const float* __restrict__ Wp, const float* __restrict__ bp,
    const float* __restrict__ W0, const float* __restrict__ b0,
    const float* __restrict__ g0, const float* __restrict__ be0,
    const float* __restrict__ W1, const float* __restrict__ b1,
    const float* __restrict__ g1, const float* __restrict__ be1)
{
    extern __shared__ float sm[];
    float* sAT  = sm;               // 256*65
    float* sX   = sAT + 256 * 65;  // 128*65
    float* sB   = sX + 128 * 65;   // 4096
    float* sInv = sB + 4096;       // 64
    int tid = threadIdx.x;
    int base = blockIdx.x * 64;
    if (tid < 64) {
        int n = min(base + tid, NNODES - 1);
        sInv[tid] = 1.0f / fmaxf(cnt[n], 1.0f);
    }
    __syncthreads();
    for (int i = tid; i < 64 * 64; i += 256) {
        int row = i / 64, c4 = i % 64;
        int n = min(base + row, NNODES - 1);
        float4 v;
        if (c4 < 32) v = *(const float4*)(h + n * DM + c4 * 4);
        else {
            v = *(const float4*)(agg + n * DM + (c4 - 32) * 4);
            float iv = sInv[row];
            v.x *= iv; v.y *= iv; v.z *= iv; v.w *= iv;
        }
        float* d = sAT + (c4 * 4) * 65 + row;
        d[0] = v.x; d[65] = v.y; d[130] = v.z; d[195] = v.w;
    }
    __syncthreads();
    int tx = tid & 15, ty = tid >> 4, c0 = tx * 8, r0 = ty * 4;
    Acc A;
    gemm_tile(Wp, bp, 256, sAT, sB, A, tid, c0, r0);
    store_T(sX, A.f, c0, r0);
    gemm_tile(W0, b0, 128, sX, sB, A, tid, c0, r0);
    gelu_ln(A, g0, be0, c0);
    store_T(sX, A.f, c0, r0);
    gemm_tile(W1, b1, 128, sX, sB, A, tid, c0, r0);
    gelu_ln(A, g1, be1, c0);
#pragma unroll
    for (int r = 0; r < 4; r++) {
        int row = r0 + r;
        int n = base + row;
#pragma unroll
        for (int j = 0; j < 8; j++)
            A.f[r * 8 + j] += sAT[(c0 + j) * 65 + row];   // residual h
        if (n < NNODES) {
            float* hp = h + n * DM + c0;
            *(float4*)hp       = *(float4*)&A.f[r * 8];
            *(float4*)(hp + 4) = *(float4*)&A.f[r * 8 + 4];
        }
    }
}

// out = LN(gelu(h @ Wout + b)) @ proj_w + proj_b
__global__ __launch_bounds__(256, 1) void out_kernel(
    const float* __restrict__ h,
    const float* __restrict__ W, const float* __restrict__ bias,
    const float* __restrict__ gg, const float* __restrict__ bb,
    const float* __restrict__ pw, const float* __restrict__ pb,
    float* __restrict__ out)
{
    extern __shared__ float sm[];
    float* sAT = sm;               // 128*65
    float* sB  = sAT + 128 * 65;  // 4096
    float* sT  = sB + 4096;       // 64*129 (row-major LN output)
    int tid = threadIdx.x;
    int base = blockIdx.x * 64;
    for (int i = tid; i < 64 * 32; i += 256) {
        int row = i / 32, c4 = i % 32;
        int n = min(base + row, NNODES - 1);
        float4 v = *(const float4*)(h + n * DM + c4 * 4);
        float* d = sAT + (c4 * 4) * 65 + row;
        d[0] = v.x; d[65] = v.y; d[130] = v.z; d[195] = v.w;
    }
    __syncthreads();
    int tx = tid & 15, ty = tid >> 4, c0 = tx * 8, r0 = ty * 4;
    Acc A;
    gemm_tile(W, bias, 128, sAT, sB, A, tid, c0, r0);
    gelu_ln(A, gg, bb, c0);
#pragma unroll
    for (int r = 0; r < 4; r++)
#pragma unroll
        for (int j = 0; j < 8; j++)
            sT[(r0 + r) * 129 + c0 + j] = A.f[r * 8 + j];
    __syncthreads();
    for (int i = tid; i < 64 * PREDL; i += 256) {
        int row = i / PREDL, oc = i % PREDL;
        int n = base + row;
        if (n < NNODES) {
            float s = pb[oc];
            const float* tr = sT + row * 129;
#pragma unroll 8
            for (int k = 0; k < 128; k++) s = fmaf(tr[k], pw[k * PREDL + oc], s);
            out[n * PREDL + oc] = s;
        }
    }
}

// ---------------- launch ------------------------------------------------------
extern "C" void kernel_launch(void* const* d_in, const int* in_sizes, int n_in,
                              void* d_out, int out_size)
{
    const float* nodes        = (const float*)d_in[0];
    const float* edges        = (const float*)d_in[1];
    const int*   senders      = (const int*)d_in[2];
    const int*   receivers    = (const int*)d_in[3];
    const float* w_node_emb   = (const float*)d_in[4];
    const float* b_node_emb   = (const float*)d_in[5];
    const float* w_edge_emb   = (const float*)d_in[6];
    const float* b_edge_emb   = (const float*)d_in[7];
    const float* edge_proj_w  = (const float*)d_in[8];
    const float* edge_proj_b  = (const float*)d_in[9];
    const float* node_proj_w  = (const float*)d_in[10];
    const float* node_proj_b  = (const float*)d_in[11];
    const float* edge_mlp_w   = (const float*)d_in[12];
    const float* edge_mlp_b   = (const float*)d_in[13];
    const float* edge_ln_g    = (const float*)d_in[14];
    const float* edge_ln_b    = (const float*)d_in[15];
    const float* node_mlp_w   = (const float*)d_in[16];
    const float* node_mlp_b   = (const float*)d_in[17];
    const float* node_ln_g    = (const float*)d_in[18];
    const float* node_ln_b    = (const float*)d_in[19];
    const float* mlp_out_w    = (const float*)d_in[20];
    const float* mlp_out_b    = (const float*)d_in[21];
    const float* mlp_out_g    = (const float*)d_in[22];
    const float* mlp_out_beta = (const float*)d_in[23];
    const float* proj_w       = (const float*)d_in[24];
    const float* proj_b       = (const float*)d_in[25];
    float* out = (float*)d_out;

    float *h, *e, *agg, *cnt;
    cudaGetSymbolAddress((void**)&h,   g_h);
    cudaGetSymbolAddress((void**)&e,   g_e);
    cudaGetSymbolAddress((void**)&agg, g_agg);
    cudaGetSymbolAddress((void**)&cnt, g_cnt);

    int smem_edge = (384 * 65 + 128 * 65 + 4096 + 128) * 4;
    int smem_node = (256 * 65 + 128 * 65 + 4096 + 64) * 4;
    int smem_emb  = (288 * 65 + 4096) * 4;
    int smem_out  = (128 * 65 + 4096 + 64 * 129) * 4;
    cudaFuncSetAttribute(edge_kernel,     cudaFuncAttributeMaxDynamicSharedMemorySize, smem_edge);
    cudaFuncSetAttribute(node_kernel,     cudaFuncAttributeMaxDynamicSharedMemorySize, smem_node);
    cudaFuncSetAttribute(emb_node_kernel, cudaFuncAttributeMaxDynamicSharedMemorySize, smem_emb);
    cudaFuncSetAttribute(out_kernel,      cudaFuncAttributeMaxDynamicSharedMemorySize, smem_out);

    int nblk = (NNODES + 63) / 64;  // 313

    cudaMemsetAsync(cnt, 0, NNODES * sizeof(float));
    emb_node_kernel<<<nblk, 256, smem_emb>>>(nodes, w_node_emb, b_node_emb, h);
    emb_edge_kernel<<<NEDGES * 32 / 256, 256>>>(edges, w_edge_emb, b_edge_emb, e);
    count_kernel<<<(NEDGES + 255) / 256, 256>>>(receivers, cnt);

    for (int l = 0; l < 2; l++) {
        cudaMemsetAsync(agg, 0, (size_t)NNODES * DM * sizeof(float));
        edge_kernel<<<NEDGES / 64, 256, smem_edge>>>(
            h, e, senders, receivers,
            edge_proj_w + l * 384 * 128, edge_proj_b + l * 128,
            edge_mlp_w + (l * 2 + 0) * 128 * 128, edge_mlp_b + (l * 2 + 0) * 128,
            edge_ln_g + (l * 2 + 0) * 128, edge_ln_b + (l * 2 + 0) * 128,
            edge_mlp_w + (l * 2 + 1) * 128 * 128, edge_mlp_b + (l * 2 + 1) * 128,
            edge_ln_g + (l * 2 + 1) * 128, edge_ln_b + (l * 2 + 1) * 128,
            agg);
        node_kernel<<<nblk, 256, smem_node>>>(
            h, agg, cnt,
            node_proj_w + l * 256 * 128, node_proj_b + l * 128,
            node_mlp_w + (l * 2 + 0) * 128 * 128, node_mlp_b + (l * 2 + 0) * 128,
            node_ln_g + (l * 2 + 0) * 128, node_ln_b + (l * 2 + 0) * 128,
            node_mlp_w + (l * 2 + 1) * 128 * 128, node_mlp_b + (l * 2 + 1) * 128,
            node_ln_g + (l * 2 + 1) * 128, node_ln_b + (l * 2 + 1) * 128);
    }
    out_kernel<<<nblk, 256, smem_out>>>(h, mlp_out_w, mlp_out_b, mlp_out_g,
                                        mlp_out_beta, proj_w, proj_b, out);
}